// round 2
// baseline (speedup 1.0000x reference)
#include <cuda_runtime.h>

// LearnedEquivariance: per-sample 5x5 circular cross-correlation applied twice
// to each of 64 channels. 8192 planes of 56x56. Fused two-pass in shared memory,
// packed f32x2 FMA math. g dtype (int32 vs int64) auto-detected in-kernel.

#define BLOCK_THREADS 224
#define ROWSTRIDE 68
#define BUF_FLOATS (60 * ROWSTRIDE)            // 4080 floats per padded plane buffer
#define SMEM_FLOATS (4 * BUF_FLOATS + 64)      // A0,A1,B0,B1 + weight scratch
#define SMEM_BYTES (SMEM_FLOATS * 4)           // 65536 bytes

typedef unsigned long long u64;

__device__ __forceinline__ u64 pack2(float lo, float hi) {
    u64 r;
    asm("mov.b64 %0, {%1, %2};" : "=l"(r) : "f"(lo), "f"(hi));
    return r;
}
__device__ __forceinline__ float2 unpack2(u64 v) {
    float2 r;
    asm("mov.b64 {%0, %1}, %2;" : "=f"(r.x), "=f"(r.y) : "l"(v));
    return r;
}
__device__ __forceinline__ void fma2(u64 &acc, u64 a, u64 b) {
    asm("fma.rn.f32x2 %0, %1, %2, %0;" : "+l"(acc) : "l"(a), "l"(b));
}

// Compute a 4-wide x 7-tall output tile of one circular 5x5 correlation pass.
// buf: padded plane, row stride 68 floats. Padded row pr <-> logical row pr-2,
// padded col pc <-> logical col pc-6 (interior rows 2..57, cols 6..61).
__device__ __forceinline__ void conv_tile(const float* __restrict__ buf,
                                          const u64* KP, int tr, int tc,
                                          u64 acc[7][2]) {
#pragma unroll
    for (int o = 0; o < 7; o++) { acc[o][0] = 0ull; acc[o][1] = 0ull; }
    const int R0 = tr * 7;
    const int c0 = tc * 4 + 4;   // first window col (16B aligned)
#pragma unroll
    for (int r = 0; r < 11; r++) {
        const float* row = buf + (R0 + r) * ROWSTRIDE + c0;
        float4 W0 = *reinterpret_cast<const float4*>(row);
        float4 W1 = *reinterpret_cast<const float4*>(row + 4);
        // window w0..w7; even pairs straight from the vectors, odd pairs repacked
        u64 E0 = pack2(W0.x, W0.y);
        u64 E1 = pack2(W0.z, W0.w);
        u64 E2 = pack2(W1.x, W1.y);
        u64 E3 = pack2(W1.z, W1.w);
        u64 O0 = pack2(W0.y, W0.z);
        u64 O1 = pack2(W0.w, W1.x);
        u64 O2 = pack2(W1.y, W1.z);
#pragma unroll
        for (int o = 0; o < 7; o++) {
            if (o > r || r > o + 4) continue;   // this input row feeds out rows r-4..r
            const int d = r - o;                // kernel row
            fma2(acc[o][0], E0, KP[d * 5 + 0]); fma2(acc[o][1], E1, KP[d * 5 + 0]);
            fma2(acc[o][0], O0, KP[d * 5 + 1]); fma2(acc[o][1], O1, KP[d * 5 + 1]);
            fma2(acc[o][0], E1, KP[d * 5 + 2]); fma2(acc[o][1], E2, KP[d * 5 + 2]);
            fma2(acc[o][0], O1, KP[d * 5 + 3]); fma2(acc[o][1], O2, KP[d * 5 + 3]);
            fma2(acc[o][0], E2, KP[d * 5 + 4]); fma2(acc[o][1], E3, KP[d * 5 + 4]);
        }
    }
}

__global__ __launch_bounds__(BLOCK_THREADS, 2)
void le_kernel(const float* __restrict__ x, const float* __restrict__ kern,
               const void* __restrict__ graw, float* __restrict__ out) {
    extern __shared__ float s[];
    const int tid = threadIdx.x;
    const int plane0 = blockIdx.x * 2;   // two (b,c) planes per block

    float* kw = s + 4 * BUF_FLOATS;

    // Warp 0: detect g dtype (int64 -> all odd int32 words of first 512B are 0;
    // int32 data has g-values there, all-zero w.p. (1/40)^64 ~ 0), then stage
    // per-plane 5x5 kernels into smem.
    if (tid < 32) {
        const int* gi32 = (const int*)graw;
        bool odd_zero = (gi32[2 * tid + 1] == 0) && (gi32[2 * tid + 65] == 0);
        unsigned m = __ballot_sync(0xffffffffu, odd_zero);
        bool is64 = (m == 0xffffffffu);
        for (int i = tid; i < 50; i += 32) {
            int wp = i / 25, wi = i - wp * 25;
            int b = (plane0 + wp) >> 6;      // plane index / 64 channels
            long long gv = is64 ? ((const long long*)graw)[b]
                                : (long long)gi32[b];
            int gi = (int)(((gv % 40) + 40) % 40);
            kw[wp * 25 + wi] = kern[gi * 25 + wi];
        }
    }

    // Fill padded A buffers (circular wrap), both planes.
    for (int idx = tid; idx < 2 * 3600; idx += BLOCK_THREADS) {
        int p = idx / 3600;
        int rem = idx - p * 3600;
        int pr = rem / 60;
        int pcc = rem - pr * 60;                 // 0..59 -> padded col pcc+4
        int li = (pr + 54) % 56;                 // logical row (pr-2) mod 56
        int lj = (pcc + 54) % 56;                // logical col (pcc-2) mod 56
        s[p * BUF_FLOATS + pr * ROWSTRIDE + pcc + 4] =
            x[(plane0 + p) * 3136 + li * 56 + lj];
    }
    __syncthreads();

    const int pl = tid / 112;            // which plane this thread computes
    const int lt = tid - pl * 112;       // tile id within plane (112 tiles)
    const int tr = lt / 14;
    const int tc = lt - tr * 14;

    // Pack weights into f32x2 register pairs (both lanes = same weight)
    u64 KP[25];
    {
        const float* kwp = kw + pl * 25;
#pragma unroll
        for (int w = 0; w < 25; w++) { float v = kwp[w]; KP[w] = pack2(v, v); }
    }

    const float* A = s + pl * BUF_FLOATS;
    float* B = s + (2 + pl) * BUF_FLOATS;

    // ---- pass 1: A -> B interior ----
    u64 acc[7][2];
    conv_tile(A, KP, tr, tc, acc);
#pragma unroll
    for (int o = 0; o < 7; o++) {
        float* dst = B + (2 + tr * 7 + o) * ROWSTRIDE + (6 + tc * 4);
        *reinterpret_cast<float2*>(dst)     = unpack2(acc[o][0]);
        *reinterpret_cast<float2*>(dst + 2) = unpack2(acc[o][1]);
    }
    __syncthreads();

    // ---- wrap B halos from interior (464 cells/plane) ----
    for (int idx = tid; idx < 2 * 3600; idx += BLOCK_THREADS) {
        int p = idx / 3600;
        int rem = idx - p * 3600;
        int pr = rem / 60;
        int pcc = rem - pr * 60;
        int pc = pcc + 4;
        if (pr >= 2 && pr < 58 && pc >= 6 && pc < 62) continue;  // interior
        float* Bq = s + (2 + p) * BUF_FLOATS;
        int prs = 2 + (pr + 54) % 56;
        int pcs = 6 + (pc + 50) % 56;
        Bq[pr * ROWSTRIDE + pc] = Bq[prs * ROWSTRIDE + pcs];
    }
    __syncthreads();

    // ---- pass 2: B -> gmem ----
    conv_tile(B, KP, tr, tc, acc);
    float* op = out + (plane0 + pl) * 3136 + tr * 7 * 56 + tc * 4;
#pragma unroll
    for (int o = 0; o < 7; o++) {
        float2 a  = unpack2(acc[o][0]);
        float2 b2 = unpack2(acc[o][1]);
        *reinterpret_cast<float4*>(op + o * 56) = make_float4(a.x, a.y, b2.x, b2.y);
    }
}

extern "C" void kernel_launch(void* const* d_in, const int* in_sizes, int n_in,
                              void* d_out, int out_size) {
    const float* x     = (const float*)d_in[0];   // [128,64,56,56] f32
    const float* kern  = (const float*)d_in[1];   // [40,5,5] f32
    const void*  g     = d_in[2];                  // [128] int32 or int64 (auto)
    // d_in[3] = l (0), d_in[4] = n (2): static in the reference, hardcoded here.
    float* out = (float*)d_out;

    cudaFuncSetAttribute(le_kernel, cudaFuncAttributeMaxDynamicSharedMemorySize,
                         SMEM_BYTES);
    // 8192 planes, 2 per block
    le_kernel<<<4096, BLOCK_THREADS, SMEM_BYTES>>>(x, kern, g, out);
}

// round 3
// speedup vs baseline: 1.1397x; 1.1397x over previous
#include <cuda_runtime.h>

// LearnedEquivariance: per-sample 5x5 circular cross-correlation applied twice.
// Channel-pair SIMD: each block handles 2 channels of one sample; smem holds the
// plane as interleaved float2 (ch0,ch1), so every fma.rn.f32x2 operand is a
// natively-aligned register pair straight out of ld.shared.v2.u64 — no packing.

#define NT 224
#define SP 64                     // pair-columns per padded row
#define BUF_U64 (60 * SP)         // 3840 float2 cells per buffer
#define SMEM_BYTES (2 * BUF_U64 * 8 + 128)

typedef unsigned long long u64;

__device__ __forceinline__ u64 pack2(float lo, float hi) {
    u64 r; asm("mov.b64 %0, {%1, %2};" : "=l"(r) : "f"(lo), "f"(hi)); return r;
}
__device__ __forceinline__ float2 unpack2(u64 v) {
    float2 r; asm("mov.b64 {%0, %1}, %2;" : "=f"(r.x), "=f"(r.y) : "l"(v)); return r;
}
__device__ __forceinline__ void fma2(u64 &acc, u64 a, u64 b) {
    asm("fma.rn.f32x2 %0, %1, %2, %0;" : "+l"(acc) : "l"(a), "l"(b));
}
__device__ __forceinline__ void lds2(u64 &a, u64 &b, unsigned addr) {
    asm volatile("ld.shared.v2.u64 {%0, %1}, [%2];" : "=l"(a), "=l"(b) : "r"(addr));
}
__device__ __forceinline__ void sts2(unsigned addr, u64 a, u64 b) {
    asm volatile("st.shared.v2.u64 [%0], {%1, %2};" :: "r"(addr), "l"(a), "l"(b));
}

// One circular 5x5 pass over a 2-wide x 7-tall tile of output channel-pairs.
// base: smem byte addr of padded cell (0,0). Padded (pr,pc) <-> logical (pr-2,pc-2).
// Out row R reads padded rows R..R+4; out cols (j,j+1) read padded pcs j..j+5.
__device__ __forceinline__ void conv14(unsigned base, const u64* __restrict__ KP,
                                       int R0, int j, u64 acc[7][2]) {
#pragma unroll
    for (int o = 0; o < 7; o++) { acc[o][0] = 0ull; acc[o][1] = 0ull; }
#pragma unroll
    for (int r = 0; r < 11; r++) {
        unsigned a = base + (unsigned)(((R0 + r) * SP + j) * 8);
        u64 P0, P1, P2, P3, P4, P5;
        lds2(P0, P1, a);
        lds2(P2, P3, a + 16);
        lds2(P4, P5, a + 32);
#pragma unroll
        for (int o = 0; o < 7; o++) {
            if (o > r || r > o + 4) continue;
            const int d = r - o;               // kernel row
            fma2(acc[o][0], P0, KP[d * 5 + 0]); fma2(acc[o][1], P1, KP[d * 5 + 0]);
            fma2(acc[o][0], P1, KP[d * 5 + 1]); fma2(acc[o][1], P2, KP[d * 5 + 1]);
            fma2(acc[o][0], P2, KP[d * 5 + 2]); fma2(acc[o][1], P3, KP[d * 5 + 2]);
            fma2(acc[o][0], P3, KP[d * 5 + 3]); fma2(acc[o][1], P4, KP[d * 5 + 3]);
            fma2(acc[o][0], P4, KP[d * 5 + 4]); fma2(acc[o][1], P5, KP[d * 5 + 4]);
        }
    }
}

__global__ __launch_bounds__(NT, 2)
void le_kernel(const float* __restrict__ x, const float* __restrict__ kern,
               const void* __restrict__ graw, float* __restrict__ out) {
    extern __shared__ float2 s2[];          // A at [0, BUF_U64), B at [BUF_U64, 2*BUF_U64)
    const int tid = threadIdx.x;
    const int plane0 = blockIdx.x * 2;      // channel-pair (same sample: 64 | channels)
    const int b = plane0 >> 6;
    float* kw = (float*)(s2 + 2 * BUF_U64); // 25 staged weights

    // Warp 0: g dtype detect (int64 -> odd int32 words of first 512B all zero),
    // then stage this sample's 5x5 kernel.
    if (tid < 32) {
        const int* gi32 = (const int*)graw;
        bool oz = (gi32[2 * tid + 1] == 0) && (gi32[2 * tid + 65] == 0);
        unsigned m = __ballot_sync(0xffffffffu, oz);
        long long gv = (m == 0xffffffffu) ? ((const long long*)graw)[b]
                                          : (long long)gi32[b];
        int gi = (int)(((gv % 40) + 40) % 40);
        if (tid < 25) kw[tid] = kern[gi * 25 + tid];
    }

    // Fill padded A (circular wrap), interleaving the two channels.
    const float* x0 = x + (long)plane0 * 3136;
    const float* x1 = x0 + 3136;
    for (int idx = tid; idx < 3600; idx += NT) {
        int pr = idx / 60, pc = idx - pr * 60;
        int li = (pr + 54) % 56, lj = (pc + 54) % 56;
        s2[pr * SP + pc] = make_float2(x0[li * 56 + lj], x1[li * 56 + lj]);
    }
    __syncthreads();

    unsigned sb;
    asm("{ .reg .u64 t; cvta.to.shared.u64 t, %1; cvt.u32.u64 %0, t; }"
        : "=r"(sb) : "l"((void*)s2));
    const unsigned Ab = sb;
    const unsigned Bb = sb + BUF_U64 * 8;

    // Broadcast weights into (w,w) register pairs.
    u64 KP[25];
#pragma unroll
    for (int w = 0; w < 25; w++) { float v = kw[w]; KP[w] = pack2(v, v); }

    const int tr = tid / 28, tc = tid - tr * 28;
    const int R0 = tr * 7, j = tc * 2;

    // ---- pass 1: A -> B interior ----
    u64 acc[7][2];
    conv14(Ab, KP, R0, j, acc);
#pragma unroll
    for (int o = 0; o < 7; o++)
        sts2(Bb + (unsigned)(((2 + R0 + o) * SP + (2 + j)) * 8), acc[o][0], acc[o][1]);
    __syncthreads();

    // ---- wrap B halos from interior (464 pair-cells) ----
    for (int idx = tid; idx < 3600; idx += NT) {
        int pr = idx / 60, pc = idx - pr * 60;
        if (pr >= 2 && pr < 58 && pc >= 2 && pc < 58) continue;
        int ps = 2 + (pr + 54) % 56, qs = 2 + (pc + 54) % 56;
        s2[BUF_U64 + pr * SP + pc] = s2[BUF_U64 + ps * SP + qs];
    }
    __syncthreads();

    // ---- pass 2: B -> gmem ----
    conv14(Bb, KP, R0, j, acc);
    float* o0 = out + (long)plane0 * 3136;
    float* o1 = o0 + 3136;
#pragma unroll
    for (int o = 0; o < 7; o++) {
        float2 a0 = unpack2(acc[o][0]), a1 = unpack2(acc[o][1]);
        int off = (R0 + o) * 56 + j;
        *reinterpret_cast<float2*>(o0 + off) = make_float2(a0.x, a1.x);
        *reinterpret_cast<float2*>(o1 + off) = make_float2(a0.y, a1.y);
    }
}

extern "C" void kernel_launch(void* const* d_in, const int* in_sizes, int n_in,
                              void* d_out, int out_size) {
    const float* x    = (const float*)d_in[0];  // [128,64,56,56] f32
    const float* kern = (const float*)d_in[1];  // [40,5,5] f32
    const void*  g    = d_in[2];                // [128] int32 or int64 (auto)
    float* out = (float*)d_out;

    cudaFuncSetAttribute(le_kernel, cudaFuncAttributeMaxDynamicSharedMemorySize,
                         SMEM_BYTES);
    le_kernel<<<4096, NT, SMEM_BYTES>>>(x, kern, g, out);  // 4096 channel-pairs
}

// round 5
// speedup vs baseline: 2.5625x; 2.2483x over previous
#include <cuda_runtime.h>

// LearnedEquivariance: per-sample 5x5 circular cross-correlation, applied twice.
// Channel-pair SIMD (fma.rn.f32x2 on interleaved float2 cells), single reused
// smem buffer, halo replication fused into pass-1 stores, 3 CTAs/SM.

#define NT 224
#define SP 64                      // pair-cells per padded row (60 used)
#define BUF_CELLS (60 * SP)        // 3840 float2 cells
#define SMEM_BYTES (BUF_CELLS * 8 + 128)

typedef unsigned long long u64;

__device__ __forceinline__ u64 pack2(float lo, float hi) {
    u64 r; asm("mov.b64 %0, {%1, %2};" : "=l"(r) : "f"(lo), "f"(hi)); return r;
}
__device__ __forceinline__ float2 unpack2(u64 v) {
    float2 r; asm("mov.b64 {%0, %1}, %2;" : "=f"(r.x), "=f"(r.y) : "l"(v)); return r;
}
__device__ __forceinline__ void fma2(u64 &acc, u64 a, u64 b) {
    asm("fma.rn.f32x2 %0, %1, %2, %0;" : "+l"(acc) : "l"(a), "l"(b));
}
__device__ __forceinline__ void lds2(u64 &a, u64 &b, unsigned addr) {
    asm volatile("ld.shared.v2.u64 {%0, %1}, [%2];" : "=l"(a), "=l"(b) : "r"(addr));
}
__device__ __forceinline__ void sts2(unsigned addr, u64 a, u64 b) {
    asm volatile("st.shared.v2.u64 [%0], {%1, %2};" :: "r"(addr), "l"(a), "l"(b));
}

// One circular 5x5 pass over a 2-wide x 7-tall tile of channel-pair outputs.
// base: smem byte addr of padded cell (0,0); padded (pr,pc) <-> logical (pr-2,pc-2).
__device__ __forceinline__ void conv14(unsigned base, const u64* __restrict__ KP,
                                       int R0, int j, u64 acc[7][2]) {
#pragma unroll
    for (int o = 0; o < 7; o++) { acc[o][0] = 0ull; acc[o][1] = 0ull; }
#pragma unroll
    for (int r = 0; r < 11; r++) {
        unsigned a = base + (unsigned)(((R0 + r) * SP + j) * 8);
        u64 P0, P1, P2, P3, P4, P5;
        lds2(P0, P1, a);
        lds2(P2, P3, a + 16);
        lds2(P4, P5, a + 32);
#pragma unroll
        for (int o = 0; o < 7; o++) {
            if (o > r || r > o + 4) continue;
            const int d = r - o;               // kernel row
            fma2(acc[o][0], P0, KP[d * 5 + 0]); fma2(acc[o][1], P1, KP[d * 5 + 0]);
            fma2(acc[o][0], P1, KP[d * 5 + 1]); fma2(acc[o][1], P2, KP[d * 5 + 1]);
            fma2(acc[o][0], P2, KP[d * 5 + 2]); fma2(acc[o][1], P3, KP[d * 5 + 2]);
            fma2(acc[o][0], P3, KP[d * 5 + 3]); fma2(acc[o][1], P4, KP[d * 5 + 3]);
            fma2(acc[o][0], P4, KP[d * 5 + 4]); fma2(acc[o][1], P5, KP[d * 5 + 4]);
        }
    }
}

__global__ __launch_bounds__(NT, 3)
void le_kernel(const float* __restrict__ x, const float* __restrict__ kern,
               const void* __restrict__ graw, float* __restrict__ out) {
    extern __shared__ float2 s2[];          // one 60x64 padded pair-plane
    const int tid = threadIdx.x;
    const int plane0 = blockIdx.x * 2;      // channel pair within one sample
    const int b = plane0 >> 6;
    float* kw = (float*)(s2 + BUF_CELLS);

    unsigned Ab;
    asm("{ .reg .u64 t; cvta.to.shared.u64 t, %1; cvt.u32.u64 %0, t; }"
        : "=r"(Ab) : "l"((void*)s2));

    // Warp 0: g dtype detect (int64 -> odd int32 words of first 512B all zero),
    // then stage this sample's 5x5 kernel.
    if (tid < 32) {
        const int* gi32 = (const int*)graw;
        bool oz = (gi32[2 * tid + 1] == 0) && (gi32[2 * tid + 65] == 0);
        unsigned m = __ballot_sync(0xffffffffu, oz);
        long long gv = (m == 0xffffffffu) ? ((const long long*)graw)[b]
                                          : (long long)gi32[b];
        int gi = (int)(((gv % 40) + 40) % 40);
        if (tid < 25) kw[tid] = kern[gi * 25 + tid];
    }

    const float* x0 = x + (long)plane0 * 3136;
    const float* x1 = x0 + 3136;

    // Interior fill: coalesced float4 loads, 4 cells per iteration.
    for (int idx = tid; idx < 784; idx += NT) {
        float4 a = *reinterpret_cast<const float4*>(x0 + idx * 4);
        float4 c = *reinterpret_cast<const float4*>(x1 + idx * 4);
        int li = (idx * 4) / 56, lj = (idx * 4) % 56;
        unsigned ad = Ab + (unsigned)(((li + 2) * SP + lj + 2) * 8);
        sts2(ad,      pack2(a.x, c.x), pack2(a.y, c.y));
        sts2(ad + 16, pack2(a.z, c.z), pack2(a.w, c.w));
    }
    // Halo fill: 464 wrap cells straight from gmem.
    // rows 0,1 (120) + rows 58,59 (120) + side cols pc in {0,1,58,59} for pr 2..57 (224).
    for (int idx = tid; idx < 464; idx += NT) {
        int pr, pc;
        if (idx < 120)      { pr = idx / 60;              pc = idx % 60; }
        else if (idx < 240) { pr = 58 + (idx - 120) / 60; pc = (idx - 120) % 60; }
        else { int t = idx - 240; pr = 2 + t / 4; int q = t % 4; pc = q < 2 ? q : 56 + q; }
        int li = (pr + 54) % 56, lj = (pc + 54) % 56;
        s2[pr * SP + pc] = make_float2(x0[li * 56 + lj], x1[li * 56 + lj]);
    }
    __syncthreads();

    u64 KP[25];
#pragma unroll
    for (int w = 0; w < 25; w++) { float v = kw[w]; KP[w] = pack2(v, v); }

    const int tr = tid / 28, tc = tid - tr * 28;
    const int R0 = tr * 7, j = tc * 2;
    const bool jlo = (tc == 0), jhi = (tc == 27);

    // ---- pass 1: read whole buffer into 14 reg accumulators ----
    u64 acc[7][2];
    conv14(Ab, KP, R0, j, acc);
    __syncthreads();   // all pass-1 reads complete before in-place overwrite

    // ---- store pass-1 results in place, with circular halo replicas ----
#pragma unroll
    for (int o = 0; o < 7; o++) {
        int i = R0 + o;
        int pr = 2 + i;
        unsigned rb = Ab + (unsigned)((pr * SP + 2 + j) * 8);
        sts2(rb, acc[o][0], acc[o][1]);
        if (jlo) sts2(Ab + (unsigned)((pr * SP + 58) * 8), acc[o][0], acc[o][1]);
        if (jhi) sts2(Ab + (unsigned)((pr * SP) * 8),      acc[o][0], acc[o][1]);
        if (i < 2 || i >= 54) {
            int pr2 = (i < 2) ? pr + 56 : pr - 56;
            sts2(Ab + (unsigned)((pr2 * SP + 2 + j) * 8), acc[o][0], acc[o][1]);
            if (jlo) sts2(Ab + (unsigned)((pr2 * SP + 58) * 8), acc[o][0], acc[o][1]);
            if (jhi) sts2(Ab + (unsigned)((pr2 * SP) * 8),      acc[o][0], acc[o][1]);
        }
    }
    __syncthreads();

    // ---- pass 2: buffer -> gmem ----
    conv14(Ab, KP, R0, j, acc);
    float* o0 = out + (long)plane0 * 3136;
    float* o1 = o0 + 3136;
#pragma unroll
    for (int o = 0; o < 7; o++) {
        float2 a0 = unpack2(acc[o][0]), a1 = unpack2(acc[o][1]);
        int off = (R0 + o) * 56 + j;
        *reinterpret_cast<float2*>(o0 + off) = make_float2(a0.x, a1.x);
        *reinterpret_cast<float2*>(o1 + off) = make_float2(a0.y, a1.y);
    }
}

extern "C" void kernel_launch(void* const* d_in, const int* in_sizes, int n_in,
                              void* d_out, int out_size) {
    const float* x    = (const float*)d_in[0];  // [128,64,56,56] f32
    const float* kern = (const float*)d_in[1];  // [40,5,5] f32
    const void*  g    = d_in[2];                // [128] int32 or int64 (auto)
    float* out = (float*)d_out;

    cudaFuncSetAttribute(le_kernel, cudaFuncAttributeMaxDynamicSharedMemorySize,
                         SMEM_BYTES);
    le_kernel<<<4096, NT, SMEM_BYTES>>>(x, kern, g, out);  // 4096 channel-pairs
}

// round 6
// speedup vs baseline: 2.8273x; 1.1034x over previous
#include <cuda_runtime.h>

// LearnedEquivariance: per-sample 5x5 circular cross-correlation, applied twice.
// Channel-pair SIMD (fma.rn.f32x2 on interleaved float2 cells), single reused
// smem buffer, halo replication fused into pass-1 stores, 4 CTAs/SM.

#define NT 224
#define SP 64                      // pair-cells per padded row (60 used)
#define BUF_CELLS (60 * SP)        // 3840 float2 cells
#define SMEM_BYTES (BUF_CELLS * 8 + 128)

typedef unsigned long long u64;

__device__ __forceinline__ u64 pack2(float lo, float hi) {
    u64 r; asm("mov.b64 %0, {%1, %2};" : "=l"(r) : "f"(lo), "f"(hi)); return r;
}
__device__ __forceinline__ float2 unpack2(u64 v) {
    float2 r; asm("mov.b64 {%0, %1}, %2;" : "=f"(r.x), "=f"(r.y) : "l"(v)); return r;
}
__device__ __forceinline__ void fma2(u64 &acc, u64 a, u64 b) {
    asm("fma.rn.f32x2 %0, %1, %2, %0;" : "+l"(acc) : "l"(a), "l"(b));
}
__device__ __forceinline__ void lds2(u64 &a, u64 &b, unsigned addr) {
    asm volatile("ld.shared.v2.u64 {%0, %1}, [%2];" : "=l"(a), "=l"(b) : "r"(addr));
}
__device__ __forceinline__ void sts2(unsigned addr, u64 a, u64 b) {
    asm volatile("st.shared.v2.u64 [%0], {%1, %2};" :: "r"(addr), "l"(a), "l"(b));
}

// One circular 5x5 pass over a 2-wide x 7-tall tile of channel-pair outputs.
// base: smem byte addr of padded cell (0,0); padded (pr,pc) <-> logical (pr-2,pc-2).
__device__ __forceinline__ void conv14(unsigned base, const u64* __restrict__ KP,
                                       int R0, int j, u64 acc[7][2]) {
#pragma unroll
    for (int o = 0; o < 7; o++) { acc[o][0] = 0ull; acc[o][1] = 0ull; }
#pragma unroll
    for (int r = 0; r < 11; r++) {
        unsigned a = base + (unsigned)(((R0 + r) * SP + j) * 8);
        u64 P0, P1, P2, P3, P4, P5;
        lds2(P0, P1, a);
        lds2(P2, P3, a + 16);
        lds2(P4, P5, a + 32);
#pragma unroll
        for (int o = 0; o < 7; o++) {
            if (o > r || r > o + 4) continue;
            const int d = r - o;               // kernel row
            fma2(acc[o][0], P0, KP[d * 5 + 0]); fma2(acc[o][1], P1, KP[d * 5 + 0]);
            fma2(acc[o][0], P1, KP[d * 5 + 1]); fma2(acc[o][1], P2, KP[d * 5 + 1]);
            fma2(acc[o][0], P2, KP[d * 5 + 2]); fma2(acc[o][1], P3, KP[d * 5 + 2]);
            fma2(acc[o][0], P3, KP[d * 5 + 3]); fma2(acc[o][1], P4, KP[d * 5 + 3]);
            fma2(acc[o][0], P4, KP[d * 5 + 4]); fma2(acc[o][1], P5, KP[d * 5 + 4]);
        }
    }
}

__global__ __launch_bounds__(NT, 4)
void le_kernel(const float* __restrict__ x, const float* __restrict__ kern,
               const void* __restrict__ graw, float* __restrict__ out) {
    extern __shared__ float2 s2[];          // one 60x64 padded pair-plane
    const int tid = threadIdx.x;
    const int plane0 = blockIdx.x * 2;      // channel pair within one sample
    const int b = plane0 >> 6;
    float* kw = (float*)(s2 + BUF_CELLS);

    unsigned Ab;
    asm("{ .reg .u64 t; cvta.to.shared.u64 t, %1; cvt.u32.u64 %0, t; }"
        : "=r"(Ab) : "l"((void*)s2));

    // Warp 0: g dtype detect (int64 -> odd int32 words of first 512B all zero),
    // then stage this sample's 5x5 kernel.
    if (tid < 32) {
        const int* gi32 = (const int*)graw;
        bool oz = (gi32[2 * tid + 1] == 0) && (gi32[2 * tid + 65] == 0);
        unsigned m = __ballot_sync(0xffffffffu, oz);
        long long gv = (m == 0xffffffffu) ? ((const long long*)graw)[b]
                                          : (long long)gi32[b];
        int gi = (int)(((gv % 40) + 40) % 40);
        if (tid < 25) kw[tid] = kern[gi * 25 + tid];
    }

    const float* x0 = x + (long)plane0 * 3136;
    const float* x1 = x0 + 3136;

    // Interior fill: coalesced float4 loads, 4 cells per iteration.
    for (int idx = tid; idx < 784; idx += NT) {
        float4 a = *reinterpret_cast<const float4*>(x0 + idx * 4);
        float4 c = *reinterpret_cast<const float4*>(x1 + idx * 4);
        int li = (idx * 4) / 56, lj = (idx * 4) % 56;
        unsigned ad = Ab + (unsigned)(((li + 2) * SP + lj + 2) * 8);
        sts2(ad,      pack2(a.x, c.x), pack2(a.y, c.y));
        sts2(ad + 16, pack2(a.z, c.z), pack2(a.w, c.w));
    }
    // Halo fill: 464 wrap cells straight from gmem.
    // rows 0,1 (120) + rows 58,59 (120) + side cols pc in {0,1,58,59} for pr 2..57 (224).
    for (int idx = tid; idx < 464; idx += NT) {
        int pr, pc;
        if (idx < 120)      { pr = idx / 60;              pc = idx % 60; }
        else if (idx < 240) { pr = 58 + (idx - 120) / 60; pc = (idx - 120) % 60; }
        else { int t = idx - 240; pr = 2 + t / 4; int q = t % 4; pc = q < 2 ? q : 56 + q; }
        int li = (pr + 54) % 56, lj = (pc + 54) % 56;
        s2[pr * SP + pc] = make_float2(x0[li * 56 + lj], x1[li * 56 + lj]);
    }
    __syncthreads();

    u64 KP[25];
#pragma unroll
    for (int w = 0; w < 25; w++) { float v = kw[w]; KP[w] = pack2(v, v); }

    const int tr = tid / 28, tc = tid - tr * 28;
    const int R0 = tr * 7, j = tc * 2;

    // ---- pass 1: read whole buffer into 14 reg accumulators ----
    u64 acc[7][2];
    conv14(Ab, KP, R0, j, acc);
    __syncthreads();   // all pass-1 reads complete before in-place overwrite

    // ---- store pass-1 results in place, with circular halo replicas ----
#pragma unroll
    for (int o = 0; o < 7; o++) {
        int i = R0 + o;
        int pr = 2 + i;
        sts2(Ab + (unsigned)((pr * SP + 2 + j) * 8), acc[o][0], acc[o][1]);
        if (tc == 0)  sts2(Ab + (unsigned)((pr * SP + 58) * 8), acc[o][0], acc[o][1]);
        if (tc == 27) sts2(Ab + (unsigned)((pr * SP) * 8),      acc[o][0], acc[o][1]);
        if (i < 2 || i >= 54) {
            int pr2 = (i < 2) ? pr + 56 : pr - 56;
            sts2(Ab + (unsigned)((pr2 * SP + 2 + j) * 8), acc[o][0], acc[o][1]);
            if (tc == 0)  sts2(Ab + (unsigned)((pr2 * SP + 58) * 8), acc[o][0], acc[o][1]);
            if (tc == 27) sts2(Ab + (unsigned)((pr2 * SP) * 8),      acc[o][0], acc[o][1]);
        }
    }
    __syncthreads();

    // ---- pass 2: buffer -> gmem ----
    conv14(Ab, KP, R0, j, acc);
    float* o0 = out + (long)plane0 * 3136;
    float* o1 = o0 + 3136;
#pragma unroll
    for (int o = 0; o < 7; o++) {
        float2 a0 = unpack2(acc[o][0]), a1 = unpack2(acc[o][1]);
        int off = (R0 + o) * 56 + j;
        *reinterpret_cast<float2*>(o0 + off) = make_float2(a0.x, a1.x);
        *reinterpret_cast<float2*>(o1 + off) = make_float2(a0.y, a1.y);
    }
}

extern "C" void kernel_launch(void* const* d_in, const int* in_sizes, int n_in,
                              void* d_out, int out_size) {
    const float* x    = (const float*)d_in[0];  // [128,64,56,56] f32
    const float* kern = (const float*)d_in[1];  // [40,5,5] f32
    const void*  g    = d_in[2];                // [128] int32 or int64 (auto)
    float* out = (float*)d_out;

    cudaFuncSetAttribute(le_kernel, cudaFuncAttributeMaxDynamicSharedMemorySize,
                         SMEM_BYTES);
    le_kernel<<<4096, NT, SMEM_BYTES>>>(x, kern, g, out);  // 4096 channel-pairs
}

// round 7
// speedup vs baseline: 2.8357x; 1.0029x over previous
#include <cuda_runtime.h>

// LearnedEquivariance: per-sample 5x5 circular cross-correlation, applied twice.
// Channel-pair SIMD (fma.rn.f32x2 on interleaved float2 cells), single reused
// smem buffer, halo replication fused into pass-1 stores, 4 CTAs/SM.
// R7: C++ vector smem accesses (no volatile asm) so ptxas can software-pipeline
// row loads across the FMA chains.

#define NT 224
#define SP 64                      // pair-cells per padded row (60 used)
#define BUF_CELLS (60 * SP)        // 3840 float2 cells
#define SMEM_BYTES (BUF_CELLS * 8 + 128)

typedef unsigned long long u64;

__device__ __forceinline__ u64 pack2(float lo, float hi) {
    u64 r; asm("mov.b64 %0, {%1, %2};" : "=l"(r) : "f"(lo), "f"(hi)); return r;
}
__device__ __forceinline__ float2 unpack2(u64 v) {
    float2 r; asm("mov.b64 {%0, %1}, %2;" : "=f"(r.x), "=f"(r.y) : "l"(v)); return r;
}
__device__ __forceinline__ void fma2(u64 &acc, u64 a, u64 b) {
    asm("fma.rn.f32x2 %0, %1, %2, %0;" : "+l"(acc) : "l"(a), "l"(b));
}

// One circular 5x5 pass over a 2-wide x 7-tall tile of channel-pair outputs.
// buf: padded pair-plane; padded (pr,pc) <-> logical (pr-2,pc-2).
__device__ __forceinline__ void conv14(const float2* __restrict__ buf,
                                       const u64* __restrict__ KP,
                                       int R0, int j, u64 acc[7][2]) {
#pragma unroll
    for (int o = 0; o < 7; o++) { acc[o][0] = 0ull; acc[o][1] = 0ull; }
#pragma unroll
    for (int r = 0; r < 11; r++) {
        const ulonglong2* p =
            reinterpret_cast<const ulonglong2*>(buf + (R0 + r) * SP + j);
        ulonglong2 q0 = p[0], q1 = p[1], q2 = p[2];
        u64 P0 = q0.x, P1 = q0.y, P2 = q1.x, P3 = q1.y, P4 = q2.x, P5 = q2.y;
#pragma unroll
        for (int o = 0; o < 7; o++) {
            if (o > r || r > o + 4) continue;
            const int d = r - o;               // kernel row
            fma2(acc[o][0], P0, KP[d * 5 + 0]); fma2(acc[o][1], P1, KP[d * 5 + 0]);
            fma2(acc[o][0], P1, KP[d * 5 + 1]); fma2(acc[o][1], P2, KP[d * 5 + 1]);
            fma2(acc[o][0], P2, KP[d * 5 + 2]); fma2(acc[o][1], P3, KP[d * 5 + 2]);
            fma2(acc[o][0], P3, KP[d * 5 + 3]); fma2(acc[o][1], P4, KP[d * 5 + 3]);
            fma2(acc[o][0], P4, KP[d * 5 + 4]); fma2(acc[o][1], P5, KP[d * 5 + 4]);
        }
    }
}

__device__ __forceinline__ void stcell(float2* dst, u64 a, u64 b) {
    *reinterpret_cast<ulonglong2*>(dst) = make_ulonglong2(a, b);
}

__global__ __launch_bounds__(NT, 4)
void le_kernel(const float* __restrict__ x, const float* __restrict__ kern,
               const void* __restrict__ graw, float* __restrict__ out) {
    extern __shared__ float2 s2[];          // one 60x64 padded pair-plane
    const int tid = threadIdx.x;
    const int plane0 = blockIdx.x * 2;      // channel pair within one sample
    const int b = plane0 >> 6;
    float* kw = (float*)(s2 + BUF_CELLS);

    // Warp 0: g dtype detect (int64 -> odd int32 words of first 512B all zero),
    // then stage this sample's 5x5 kernel.
    if (tid < 32) {
        const int* gi32 = (const int*)graw;
        bool oz = (gi32[2 * tid + 1] == 0) && (gi32[2 * tid + 65] == 0);
        unsigned m = __ballot_sync(0xffffffffu, oz);
        long long gv = (m == 0xffffffffu) ? ((const long long*)graw)[b]
                                          : (long long)gi32[b];
        int gi = (int)(((gv % 40) + 40) % 40);
        if (tid < 25) kw[tid] = kern[gi * 25 + tid];
    }

    const float* x0 = x + (long)plane0 * 3136;
    const float* x1 = x0 + 3136;

    // Interior fill: coalesced float4 loads, 4 cells per iteration.
    for (int idx = tid; idx < 784; idx += NT) {
        float4 a = *reinterpret_cast<const float4*>(x0 + idx * 4);
        float4 c = *reinterpret_cast<const float4*>(x1 + idx * 4);
        int li = (idx * 4) / 56, lj = (idx * 4) % 56;
        float2* ad = s2 + (li + 2) * SP + lj + 2;
        stcell(ad,     pack2(a.x, c.x), pack2(a.y, c.y));
        stcell(ad + 2, pack2(a.z, c.z), pack2(a.w, c.w));
    }
    // Halo fill: 464 wrap cells straight from gmem.
    // rows 0,1 (120) + rows 58,59 (120) + side cols pc in {0,1,58,59} for pr 2..57.
    for (int idx = tid; idx < 464; idx += NT) {
        int pr, pc;
        if (idx < 120)      { pr = idx / 60;              pc = idx % 60; }
        else if (idx < 240) { pr = 58 + (idx - 120) / 60; pc = (idx - 120) % 60; }
        else { int t = idx - 240; pr = 2 + t / 4; int q = t % 4; pc = q < 2 ? q : 56 + q; }
        int li = (pr + 54) % 56, lj = (pc + 54) % 56;
        s2[pr * SP + pc] = make_float2(x0[li * 56 + lj], x1[li * 56 + lj]);
    }
    __syncthreads();

    u64 KP[25];
#pragma unroll
    for (int w = 0; w < 25; w++) { float v = kw[w]; KP[w] = pack2(v, v); }

    const int tr = tid / 28, tc = tid - tr * 28;
    const int R0 = tr * 7, j = tc * 2;

    // ---- pass 1: read whole buffer into 14 reg accumulators ----
    u64 acc[7][2];
    conv14(s2, KP, R0, j, acc);
    __syncthreads();   // all pass-1 reads complete before in-place overwrite

    // ---- store pass-1 results in place, with circular halo replicas ----
#pragma unroll
    for (int o = 0; o < 7; o++) {
        int i = R0 + o;
        int pr = 2 + i;
        stcell(s2 + pr * SP + 2 + j, acc[o][0], acc[o][1]);
        if (tc == 0)  stcell(s2 + pr * SP + 58, acc[o][0], acc[o][1]);
        if (tc == 27) stcell(s2 + pr * SP,      acc[o][0], acc[o][1]);
        if (i < 2 || i >= 54) {
            int pr2 = (i < 2) ? pr + 56 : pr - 56;
            stcell(s2 + pr2 * SP + 2 + j, acc[o][0], acc[o][1]);
            if (tc == 0)  stcell(s2 + pr2 * SP + 58, acc[o][0], acc[o][1]);
            if (tc == 27) stcell(s2 + pr2 * SP,      acc[o][0], acc[o][1]);
        }
    }
    __syncthreads();

    // ---- pass 2: buffer -> gmem ----
    conv14(s2, KP, R0, j, acc);
    float* o0 = out + (long)plane0 * 3136;
    float* o1 = o0 + 3136;
#pragma unroll
    for (int o = 0; o < 7; o++) {
        float2 a0 = unpack2(acc[o][0]), a1 = unpack2(acc[o][1]);
        int off = (R0 + o) * 56 + j;
        *reinterpret_cast<float2*>(o0 + off) = make_float2(a0.x, a1.x);
        *reinterpret_cast<float2*>(o1 + off) = make_float2(a0.y, a1.y);
    }
}

extern "C" void kernel_launch(void* const* d_in, const int* in_sizes, int n_in,
                              void* d_out, int out_size) {
    const float* x    = (const float*)d_in[0];  // [128,64,56,56] f32
    const float* kern = (const float*)d_in[1];  // [40,5,5] f32
    const void*  g    = d_in[2];                // [128] int32 or int64 (auto)
    float* out = (float*)d_out;

    cudaFuncSetAttribute(le_kernel, cudaFuncAttributeMaxDynamicSharedMemorySize,
                         SMEM_BYTES);
    le_kernel<<<4096, NT, SMEM_BYTES>>>(x, kern, g, out);  // one pair-plane/block
}

// round 8
// speedup vs baseline: 3.0895x; 1.0895x over previous
#include <cuda_runtime.h>

// LearnedEquivariance: per-sample 5x5 circular cross-correlation, applied twice.
// Channel-pair SIMD (fma.rn.f32x2 on interleaved float2 cells), single reused
// smem buffer, halo replication fused into pass-1 stores.
// R8: 5 CTAs/SM (reg cap 56) — trade per-thread ILP for +25% warps.

#define NT 224
#define SP 64                      // pair-cells per padded row (60 used)
#define BUF_CELLS (60 * SP)        // 3840 float2 cells
#define SMEM_BYTES (BUF_CELLS * 8 + 128)

typedef unsigned long long u64;

__device__ __forceinline__ u64 pack2(float lo, float hi) {
    u64 r; asm("mov.b64 %0, {%1, %2};" : "=l"(r) : "f"(lo), "f"(hi)); return r;
}
__device__ __forceinline__ float2 unpack2(u64 v) {
    float2 r; asm("mov.b64 {%0, %1}, %2;" : "=f"(r.x), "=f"(r.y) : "l"(v)); return r;
}
__device__ __forceinline__ void fma2(u64 &acc, u64 a, u64 b) {
    asm("fma.rn.f32x2 %0, %1, %2, %0;" : "+l"(acc) : "l"(a), "l"(b));
}

// One circular 5x5 pass over a 2-wide x 7-tall tile of channel-pair outputs.
// buf: padded pair-plane; padded (pr,pc) <-> logical (pr-2,pc-2).
__device__ __forceinline__ void conv14(const float2* __restrict__ buf,
                                       const u64* __restrict__ KP,
                                       int R0, int j, u64 acc[7][2]) {
#pragma unroll
    for (int o = 0; o < 7; o++) { acc[o][0] = 0ull; acc[o][1] = 0ull; }
#pragma unroll
    for (int r = 0; r < 11; r++) {
        const ulonglong2* p =
            reinterpret_cast<const ulonglong2*>(buf + (R0 + r) * SP + j);
        ulonglong2 q0 = p[0], q1 = p[1], q2 = p[2];
        u64 P0 = q0.x, P1 = q0.y, P2 = q1.x, P3 = q1.y, P4 = q2.x, P5 = q2.y;
#pragma unroll
        for (int o = 0; o < 7; o++) {
            if (o > r || r > o + 4) continue;
            const int d = r - o;               // kernel row
            fma2(acc[o][0], P0, KP[d * 5 + 0]); fma2(acc[o][1], P1, KP[d * 5 + 0]);
            fma2(acc[o][0], P1, KP[d * 5 + 1]); fma2(acc[o][1], P2, KP[d * 5 + 1]);
            fma2(acc[o][0], P2, KP[d * 5 + 2]); fma2(acc[o][1], P3, KP[d * 5 + 2]);
            fma2(acc[o][0], P3, KP[d * 5 + 3]); fma2(acc[o][1], P4, KP[d * 5 + 3]);
            fma2(acc[o][0], P4, KP[d * 5 + 4]); fma2(acc[o][1], P5, KP[d * 5 + 4]);
        }
    }
}

__device__ __forceinline__ void stcell(float2* dst, u64 a, u64 b) {
    *reinterpret_cast<ulonglong2*>(dst) = make_ulonglong2(a, b);
}

__global__ __launch_bounds__(NT, 5)
void le_kernel(const float* __restrict__ x, const float* __restrict__ kern,
               const void* __restrict__ graw, float* __restrict__ out) {
    extern __shared__ float2 s2[];          // one 60x64 padded pair-plane
    const int tid = threadIdx.x;
    const int plane0 = blockIdx.x * 2;      // channel pair within one sample
    const int b = plane0 >> 6;
    float* kw = (float*)(s2 + BUF_CELLS);

    // Warp 0: g dtype detect (int64 -> odd int32 words of first 512B all zero),
    // then stage this sample's 5x5 kernel.
    if (tid < 32) {
        const int* gi32 = (const int*)graw;
        bool oz = (gi32[2 * tid + 1] == 0) && (gi32[2 * tid + 65] == 0);
        unsigned m = __ballot_sync(0xffffffffu, oz);
        long long gv = (m == 0xffffffffu) ? ((const long long*)graw)[b]
                                          : (long long)gi32[b];
        int gi = (int)(((gv % 40) + 40) % 40);
        if (tid < 25) kw[tid] = kern[gi * 25 + tid];
    }

    const float* x0 = x + (long)plane0 * 3136;
    const float* x1 = x0 + 3136;

    // Interior fill: coalesced float4 loads, 4 cells per iteration.
    for (int idx = tid; idx < 784; idx += NT) {
        float4 a = *reinterpret_cast<const float4*>(x0 + idx * 4);
        float4 c = *reinterpret_cast<const float4*>(x1 + idx * 4);
        int li = (idx * 4) / 56, lj = (idx * 4) % 56;
        float2* ad = s2 + (li + 2) * SP + lj + 2;
        stcell(ad,     pack2(a.x, c.x), pack2(a.y, c.y));
        stcell(ad + 2, pack2(a.z, c.z), pack2(a.w, c.w));
    }
    // Halo fill: 464 wrap cells straight from gmem.
    // rows 0,1 (120) + rows 58,59 (120) + side cols pc in {0,1,58,59} for pr 2..57.
    for (int idx = tid; idx < 464; idx += NT) {
        int pr, pc;
        if (idx < 120)      { pr = idx / 60;              pc = idx % 60; }
        else if (idx < 240) { pr = 58 + (idx - 120) / 60; pc = (idx - 120) % 60; }
        else { int t = idx - 240; pr = 2 + t / 4; int q = t % 4; pc = q < 2 ? q : 56 + q; }
        int li = (pr + 54) % 56, lj = (pc + 54) % 56;
        s2[pr * SP + pc] = make_float2(x0[li * 56 + lj], x1[li * 56 + lj]);
    }
    __syncthreads();

    u64 KP[25];
#pragma unroll
    for (int w = 0; w < 25; w++) { float v = kw[w]; KP[w] = pack2(v, v); }

    const int tr = tid / 28, tc = tid - tr * 28;
    const int R0 = tr * 7, j = tc * 2;

    // ---- pass 1: read whole buffer into 14 reg accumulators ----
    u64 acc[7][2];
    conv14(s2, KP, R0, j, acc);
    __syncthreads();   // all pass-1 reads complete before in-place overwrite

    // ---- store pass-1 results in place, with circular halo replicas ----
#pragma unroll
    for (int o = 0; o < 7; o++) {
        int i = R0 + o;
        int pr = 2 + i;
        stcell(s2 + pr * SP + 2 + j, acc[o][0], acc[o][1]);
        if (tc == 0)  stcell(s2 + pr * SP + 58, acc[o][0], acc[o][1]);
        if (tc == 27) stcell(s2 + pr * SP,      acc[o][0], acc[o][1]);
        if (i < 2 || i >= 54) {
            int pr2 = (i < 2) ? pr + 56 : pr - 56;
            stcell(s2 + pr2 * SP + 2 + j, acc[o][0], acc[o][1]);
            if (tc == 0)  stcell(s2 + pr2 * SP + 58, acc[o][0], acc[o][1]);
            if (tc == 27) stcell(s2 + pr2 * SP,      acc[o][0], acc[o][1]);
        }
    }
    __syncthreads();

    // ---- pass 2: buffer -> gmem ----
    conv14(s2, KP, R0, j, acc);
    float* o0 = out + (long)plane0 * 3136;
    float* o1 = o0 + 3136;
#pragma unroll
    for (int o = 0; o < 7; o++) {
        float2 a0 = unpack2(acc[o][0]), a1 = unpack2(acc[o][1]);
        int off = (R0 + o) * 56 + j;
        *reinterpret_cast<float2*>(o0 + off) = make_float2(a0.x, a1.x);
        *reinterpret_cast<float2*>(o1 + off) = make_float2(a0.y, a1.y);
    }
}

extern "C" void kernel_launch(void* const* d_in, const int* in_sizes, int n_in,
                              void* d_out, int out_size) {
    const float* x    = (const float*)d_in[0];  // [128,64,56,56] f32
    const float* kern = (const float*)d_in[1];  // [40,5,5] f32
    const void*  g    = d_in[2];                // [128] int32 or int64 (auto)
    float* out = (float*)d_out;

    cudaFuncSetAttribute(le_kernel, cudaFuncAttributeMaxDynamicSharedMemorySize,
                         SMEM_BYTES);
    le_kernel<<<4096, NT, SMEM_BYTES>>>(x, kern, g, out);  // one pair-plane/block
}

// round 9
// speedup vs baseline: 3.1636x; 1.0240x over previous
#include <cuda_runtime.h>

// LearnedEquivariance: per-sample 5x5 circular cross-correlation, applied twice.
// Channel-pair SIMD (fma.rn.f32x2 on interleaved float2 cells), single reused
// smem buffer, halo replication fused into pass-1 stores.
// R9: 6 CTAs/SM (reg cap 48) — occupancy lever, third application.

#define NT 224
#define SP 64                      // pair-cells per padded row (60 used)
#define BUF_CELLS (60 * SP)        // 3840 float2 cells
#define SMEM_BYTES (BUF_CELLS * 8 + 128)

typedef unsigned long long u64;

__device__ __forceinline__ u64 pack2(float lo, float hi) {
    u64 r; asm("mov.b64 %0, {%1, %2};" : "=l"(r) : "f"(lo), "f"(hi)); return r;
}
__device__ __forceinline__ float2 unpack2(u64 v) {
    float2 r; asm("mov.b64 {%0, %1}, %2;" : "=f"(r.x), "=f"(r.y) : "l"(v)); return r;
}
__device__ __forceinline__ void fma2(u64 &acc, u64 a, u64 b) {
    asm("fma.rn.f32x2 %0, %1, %2, %0;" : "+l"(acc) : "l"(a), "l"(b));
}

// One circular 5x5 pass over a 2-wide x 7-tall tile of channel-pair outputs.
// buf: padded pair-plane; padded (pr,pc) <-> logical (pr-2,pc-2).
__device__ __forceinline__ void conv14(const float2* __restrict__ buf,
                                       const u64* __restrict__ KP,
                                       int R0, int j, u64 acc[7][2]) {
#pragma unroll
    for (int o = 0; o < 7; o++) { acc[o][0] = 0ull; acc[o][1] = 0ull; }
#pragma unroll
    for (int r = 0; r < 11; r++) {
        const ulonglong2* p =
            reinterpret_cast<const ulonglong2*>(buf + (R0 + r) * SP + j);
        ulonglong2 q0 = p[0], q1 = p[1], q2 = p[2];
        u64 P0 = q0.x, P1 = q0.y, P2 = q1.x, P3 = q1.y, P4 = q2.x, P5 = q2.y;
#pragma unroll
        for (int o = 0; o < 7; o++) {
            if (o > r || r > o + 4) continue;
            const int d = r - o;               // kernel row
            fma2(acc[o][0], P0, KP[d * 5 + 0]); fma2(acc[o][1], P1, KP[d * 5 + 0]);
            fma2(acc[o][0], P1, KP[d * 5 + 1]); fma2(acc[o][1], P2, KP[d * 5 + 1]);
            fma2(acc[o][0], P2, KP[d * 5 + 2]); fma2(acc[o][1], P3, KP[d * 5 + 2]);
            fma2(acc[o][0], P3, KP[d * 5 + 3]); fma2(acc[o][1], P4, KP[d * 5 + 3]);
            fma2(acc[o][0], P4, KP[d * 5 + 4]); fma2(acc[o][1], P5, KP[d * 5 + 4]);
        }
    }
}

__device__ __forceinline__ void stcell(float2* dst, u64 a, u64 b) {
    *reinterpret_cast<ulonglong2*>(dst) = make_ulonglong2(a, b);
}

__global__ __launch_bounds__(NT, 6)
void le_kernel(const float* __restrict__ x, const float* __restrict__ kern,
               const void* __restrict__ graw, float* __restrict__ out) {
    extern __shared__ float2 s2[];          // one 60x64 padded pair-plane
    const int tid = threadIdx.x;
    const int plane0 = blockIdx.x * 2;      // channel pair within one sample
    const int b = plane0 >> 6;
    float* kw = (float*)(s2 + BUF_CELLS);

    // Warp 0: g dtype detect (int64 -> odd int32 words of first 512B all zero),
    // then stage this sample's 5x5 kernel.
    if (tid < 32) {
        const int* gi32 = (const int*)graw;
        bool oz = (gi32[2 * tid + 1] == 0) && (gi32[2 * tid + 65] == 0);
        unsigned m = __ballot_sync(0xffffffffu, oz);
        long long gv = (m == 0xffffffffu) ? ((const long long*)graw)[b]
                                          : (long long)gi32[b];
        int gi = (int)(((gv % 40) + 40) % 40);
        if (tid < 25) kw[tid] = kern[gi * 25 + tid];
    }

    const float* x0 = x + (long)plane0 * 3136;
    const float* x1 = x0 + 3136;

    // Interior fill: coalesced float4 loads, 4 cells per iteration.
    for (int idx = tid; idx < 784; idx += NT) {
        float4 a = *reinterpret_cast<const float4*>(x0 + idx * 4);
        float4 c = *reinterpret_cast<const float4*>(x1 + idx * 4);
        int li = (idx * 4) / 56, lj = (idx * 4) % 56;
        float2* ad = s2 + (li + 2) * SP + lj + 2;
        stcell(ad,     pack2(a.x, c.x), pack2(a.y, c.y));
        stcell(ad + 2, pack2(a.z, c.z), pack2(a.w, c.w));
    }
    // Halo fill: 464 wrap cells straight from gmem.
    // rows 0,1 (120) + rows 58,59 (120) + side cols pc in {0,1,58,59} for pr 2..57.
    for (int idx = tid; idx < 464; idx += NT) {
        int pr, pc;
        if (idx < 120)      { pr = idx / 60;              pc = idx % 60; }
        else if (idx < 240) { pr = 58 + (idx - 120) / 60; pc = (idx - 120) % 60; }
        else { int t = idx - 240; pr = 2 + t / 4; int q = t % 4; pc = q < 2 ? q : 56 + q; }
        int li = (pr + 54) % 56, lj = (pc + 54) % 56;
        s2[pr * SP + pc] = make_float2(x0[li * 56 + lj], x1[li * 56 + lj]);
    }
    __syncthreads();

    u64 KP[25];
#pragma unroll
    for (int w = 0; w < 25; w++) { float v = kw[w]; KP[w] = pack2(v, v); }

    const int tr = tid / 28, tc = tid - tr * 28;
    const int R0 = tr * 7, j = tc * 2;

    // ---- pass 1: read whole buffer into 14 reg accumulators ----
    u64 acc[7][2];
    conv14(s2, KP, R0, j, acc);
    __syncthreads();   // all pass-1 reads complete before in-place overwrite

    // ---- store pass-1 results in place, with circular halo replicas ----
#pragma unroll
    for (int o = 0; o < 7; o++) {
        int i = R0 + o;
        int pr = 2 + i;
        stcell(s2 + pr * SP + 2 + j, acc[o][0], acc[o][1]);
        if (tc == 0)  stcell(s2 + pr * SP + 58, acc[o][0], acc[o][1]);
        if (tc == 27) stcell(s2 + pr * SP,      acc[o][0], acc[o][1]);
        if (i < 2 || i >= 54) {
            int pr2 = (i < 2) ? pr + 56 : pr - 56;
            stcell(s2 + pr2 * SP + 2 + j, acc[o][0], acc[o][1]);
            if (tc == 0)  stcell(s2 + pr2 * SP + 58, acc[o][0], acc[o][1]);
            if (tc == 27) stcell(s2 + pr2 * SP,      acc[o][0], acc[o][1]);
        }
    }
    __syncthreads();

    // ---- pass 2: buffer -> gmem ----
    conv14(s2, KP, R0, j, acc);
    float* o0 = out + (long)plane0 * 3136;
    float* o1 = o0 + 3136;
#pragma unroll
    for (int o = 0; o < 7; o++) {
        float2 a0 = unpack2(acc[o][0]), a1 = unpack2(acc[o][1]);
        int off = (R0 + o) * 56 + j;
        *reinterpret_cast<float2*>(o0 + off) = make_float2(a0.x, a1.x);
        *reinterpret_cast<float2*>(o1 + off) = make_float2(a0.y, a1.y);
    }
}

extern "C" void kernel_launch(void* const* d_in, const int* in_sizes, int n_in,
                              void* d_out, int out_size) {
    const float* x    = (const float*)d_in[0];  // [128,64,56,56] f32
    const float* kern = (const float*)d_in[1];  // [40,5,5] f32
    const void*  g    = d_in[2];                // [128] int32 or int64 (auto)
    float* out = (float*)d_out;

    cudaFuncSetAttribute(le_kernel, cudaFuncAttributeMaxDynamicSharedMemorySize,
                         SMEM_BYTES);
    le_kernel<<<4096, NT, SMEM_BYTES>>>(x, kern, g, out);  // one pair-plane/block
}